// round 3
// baseline (speedup 1.0000x reference)
#include <cuda_runtime.h>
#include <cuda_bf16.h>
#include <cstdint>

// ---------------------------------------------------------------------------
// cls_model: FPS (cycle-collapsed) -> KNN(32) -> conv1x1 stack -> maxpool -> MLP
// B=4, N=16384, C=3, N_C=1024, K=32
// ---------------------------------------------------------------------------

#define NB 4
#define NPTS 16384
#define NC 1024
#define KNN 32

// ---- device scratch (no allocations allowed) ----
__device__ int   g_cnt[NB];                       // distinct centroid count per batch
__device__ float g_cent[NB * NC * 3];             // distinct centroid coords
__device__ float g_nbr[NB * NC * KNN * 3];        // gathered neighbor coords
__device__ float g_h4[(size_t)NB * NC * KNN * 128]; // conv4 activations (64MB)
__device__ int   g_pool[NB * 1024];               // maxpool accumulator (float bits, >=0)

static __device__ __forceinline__ float f_inf() { return __int_as_float(0x7f800000); }

// ===========================================================================
// K1: FPS with cycle detection. One block per batch, 512 threads, 32 pts/thread
// in registers. Also zeroes g_pool.
// Exact arithmetic: d = ((dx*dx + dy*dy) + dz*dz), no FMA contraction,
// argmax tie -> lowest index (matches jnp.argmax).
// ===========================================================================
__global__ __launch_bounds__(512) void k_fps(const float* __restrict__ x,
                                             const int* __restrict__ far0) {
    const int b = blockIdx.x;
    const int t = threadIdx.x;
    const float* xb = x + (size_t)b * NPTS * 3;

    float px[32], py[32], pz[32];
#pragma unroll
    for (int i = 0; i < 32; i++) {
        int n = i * 512 + t;
        px[i] = xb[n * 3 + 0];
        py[i] = xb[n * 3 + 1];
        pz[i] = xb[n * 3 + 2];
    }

    __shared__ unsigned seen[512];
    __shared__ float cc[3];
    __shared__ float rd[16]; __shared__ int rn[16];
    __shared__ float rx[16], ry[16], rz[16];
    __shared__ int sdone;

    // reset pool for this launch (graph replays reuse device globals)
    g_pool[b * 1024 + t] = 0;
    g_pool[b * 1024 + 512 + t] = 0;
    seen[t] = 0u;   // t in [0,512)
    __syncthreads();

    if (t == 0) {
        int f = far0[b];
        seen[f >> 5] = 1u << (f & 31);
        float cx = xb[f * 3 + 0], cy = xb[f * 3 + 1], cz = xb[f * 3 + 2];
        cc[0] = cx; cc[1] = cy; cc[2] = cz;
        g_cent[(b * NC + 0) * 3 + 0] = cx;
        g_cent[(b * NC + 0) * 3 + 1] = cy;
        g_cent[(b * NC + 0) * 3 + 2] = cz;
        sdone = 0;
    }
    __syncthreads();

    int cnt = 1;
    for (int it = 1; it < NC; it++) {
        float cx = cc[0], cy = cc[1], cz = cc[2];
        float best = -1.0f; int bn = 0;
        float bx = 0.f, by = 0.f, bz = 0.f;
#pragma unroll
        for (int i = 0; i < 32; i++) {
            float dx = __fsub_rn(px[i], cx);
            float dy = __fsub_rn(py[i], cy);
            float dz = __fsub_rn(pz[i], cz);
            float d = __fadd_rn(__fadd_rn(__fmul_rn(dx, dx), __fmul_rn(dy, dy)),
                                __fmul_rn(dz, dz));
            int n = i * 512 + t;
            if (d > best) { best = d; bn = n; bx = px[i]; by = py[i]; bz = pz[i]; }
        }
        // warp argmax (lex: larger d, then smaller index)
#pragma unroll
        for (int o = 16; o > 0; o >>= 1) {
            float od = __shfl_down_sync(0xffffffffu, best, o);
            int   on = __shfl_down_sync(0xffffffffu, bn,   o);
            float ox = __shfl_down_sync(0xffffffffu, bx,   o);
            float oy = __shfl_down_sync(0xffffffffu, by,   o);
            float oz = __shfl_down_sync(0xffffffffu, bz,   o);
            if (od > best || (od == best && on < bn)) {
                best = od; bn = on; bx = ox; by = oy; bz = oz;
            }
        }
        int w = t >> 5;
        if ((t & 31) == 0) { rd[w] = best; rn[w] = bn; rx[w] = bx; ry[w] = by; rz[w] = bz; }
        __syncthreads();
        if (t == 0) {
            best = rd[0]; bn = rn[0]; bx = rx[0]; by = ry[0]; bz = rz[0];
            for (int j = 1; j < 16; j++) {
                if (rd[j] > best || (rd[j] == best && rn[j] < bn)) {
                    best = rd[j]; bn = rn[j]; bx = rx[j]; by = ry[j]; bz = rz[j];
                }
            }
            unsigned bit = 1u << (bn & 31);
            if (seen[bn >> 5] & bit) {
                sdone = 1;             // cycle: all future centroids are repeats
            } else {
                seen[bn >> 5] |= bit;
                g_cent[(b * NC + cnt) * 3 + 0] = bx;
                g_cent[(b * NC + cnt) * 3 + 1] = by;
                g_cent[(b * NC + cnt) * 3 + 2] = bz;
                cc[0] = bx; cc[1] = by; cc[2] = bz;
            }
        }
        __syncthreads();
        if (sdone) break;
        cnt++;
    }
    if (t == 0) g_cnt[b] = cnt;
}

// ===========================================================================
// K2: top-32 nearest points per distinct centroid. One block (256 thr) per
// centroid; d2 kept in registers (64/thread); 32 iterative lex-min rounds.
// d2 formula matches reference exactly: (c2 + x2) - 2*dot, each op rounded.
// ===========================================================================
__global__ __launch_bounds__(256) void k_knn(const float* __restrict__ x) {
    const int ci = blockIdx.x, b = blockIdx.y;
    if (ci >= g_cnt[b]) return;
    const int t = threadIdx.x;
    const float* xb = x + (size_t)b * NPTS * 3;

    const float cx = g_cent[(b * NC + ci) * 3 + 0];
    const float cy = g_cent[(b * NC + ci) * 3 + 1];
    const float cz = g_cent[(b * NC + ci) * 3 + 2];
    const float c2 = __fadd_rn(__fadd_rn(__fmul_rn(cx, cx), __fmul_rn(cy, cy)),
                               __fmul_rn(cz, cz));

    float d[64];
#pragma unroll
    for (int i = 0; i < 64; i++) {
        int n = i * 256 + t;
        float X = xb[n * 3 + 0], Y = xb[n * 3 + 1], Z = xb[n * 3 + 2];
        float x2 = __fadd_rn(__fadd_rn(__fmul_rn(X, X), __fmul_rn(Y, Y)),
                             __fmul_rn(Z, Z));
        float dt = __fadd_rn(__fadd_rn(__fmul_rn(cx, X), __fmul_rn(cy, Y)),
                             __fmul_rn(cz, Z));
        d[i] = __fsub_rn(__fadd_rn(c2, x2), __fmul_rn(2.0f, dt));
    }

    __shared__ float sd[8]; __shared__ int sn[8];
    __shared__ int s_w;
    __shared__ int wlist[KNN];

    for (int r = 0; r < KNN; r++) {
        float best = f_inf(); int bn = 1 << 30;
#pragma unroll
        for (int i = 0; i < 64; i++) {
            int n = i * 256 + t;
            if (d[i] < best || (d[i] == best && n < bn)) { best = d[i]; bn = n; }
        }
#pragma unroll
        for (int o = 16; o > 0; o >>= 1) {
            float od = __shfl_down_sync(0xffffffffu, best, o);
            int   on = __shfl_down_sync(0xffffffffu, bn,   o);
            if (od < best || (od == best && on < bn)) { best = od; bn = on; }
        }
        int w = t >> 5;
        if ((t & 31) == 0) { sd[w] = best; sn[w] = bn; }
        __syncthreads();
        if (t == 0) {
            best = sd[0]; bn = sn[0];
            for (int j = 1; j < 8; j++)
                if (sd[j] < best || (sd[j] == best && sn[j] < bn)) { best = sd[j]; bn = sn[j]; }
            s_w = bn;
            wlist[r] = bn;
        }
        __syncthreads();
        int wn = s_w;
#pragma unroll
        for (int i = 0; i < 64; i++)
            if ((i << 8) + t == wn) d[i] = f_inf();
    }
    __syncthreads();
    if (t < KNN) {
        int n = wlist[t];
        float* o = g_nbr + ((size_t)(b * NC + ci) * KNN + t) * 3;
        o[0] = xb[n * 3 + 0];
        o[1] = xb[n * 3 + 1];
        o[2] = xb[n * 3 + 2];
    }
}

// ===========================================================================
// K3a: conv1..conv4 for one centroid's 32 positions. 128 threads.
// Activations staged in padded smem (bank-conflict-free); h4 -> g_h4.
// ===========================================================================
__global__ __launch_bounds__(128) void k_conv14(
    const float* __restrict__ w1, const float* __restrict__ b1,
    const float* __restrict__ w2, const float* __restrict__ b2,
    const float* __restrict__ w3, const float* __restrict__ b3,
    const float* __restrict__ w4, const float* __restrict__ b4) {
    const int ci = blockIdx.x, b = blockIdx.y;
    if (ci >= g_cnt[b]) return;
    const int t = threadIdx.x;

    __shared__ float P[32][4];
    __shared__ float Ha[32][65];
    __shared__ float Hb[32][65];

    const float* nb = g_nbr + (size_t)(b * NC + ci) * KNN * 3;
    if (t < 96) P[t / 3][t % 3] = nb[t];
    __syncthreads();

    // conv1: 3 -> 64
    {
        int ch = t >> 1, p0 = (t & 1) * 16;
        float wa = __ldg(w1 + ch * 3 + 0), wb = __ldg(w1 + ch * 3 + 1),
              wc = __ldg(w1 + ch * 3 + 2), bb = __ldg(b1 + ch);
#pragma unroll
        for (int p = 0; p < 16; p++) {
            float v = fmaf(wa, P[p0 + p][0],
                     fmaf(wb, P[p0 + p][1],
                     fmaf(wc, P[p0 + p][2], bb)));
            Ha[p0 + p][ch] = fmaxf(v, 0.0f);
        }
    }
    __syncthreads();
    // conv2: 64 -> 64  (Ha -> Hb)
    {
        int ch = t >> 1, p0 = (t & 1) * 16;
        float acc[16];
        float bb = __ldg(b2 + ch);
#pragma unroll
        for (int p = 0; p < 16; p++) acc[p] = bb;
        for (int j = 0; j < 64; j++) {
            float w = __ldg(w2 + ch * 64 + j);
#pragma unroll
            for (int p = 0; p < 16; p++) acc[p] = fmaf(w, Ha[p0 + p][j], acc[p]);
        }
#pragma unroll
        for (int p = 0; p < 16; p++) Hb[p0 + p][ch] = fmaxf(acc[p], 0.0f);
    }
    __syncthreads();
    // conv3: 64 -> 64  (Hb -> Ha)
    {
        int ch = t >> 1, p0 = (t & 1) * 16;
        float acc[16];
        float bb = __ldg(b3 + ch);
#pragma unroll
        for (int p = 0; p < 16; p++) acc[p] = bb;
        for (int j = 0; j < 64; j++) {
            float w = __ldg(w3 + ch * 64 + j);
#pragma unroll
            for (int p = 0; p < 16; p++) acc[p] = fmaf(w, Hb[p0 + p][j], acc[p]);
        }
#pragma unroll
        for (int p = 0; p < 16; p++) Ha[p0 + p][ch] = fmaxf(acc[p], 0.0f);
    }
    __syncthreads();
    // conv4: 64 -> 128 (Ha -> g_h4)
    {
        float acc[32];
        float bb = __ldg(b4 + t);
#pragma unroll
        for (int p = 0; p < 32; p++) acc[p] = bb;
        for (int j = 0; j < 64; j++) {
            float w = __ldg(w4 + t * 64 + j);
#pragma unroll
            for (int p = 0; p < 32; p++) acc[p] = fmaf(w, Ha[p][j], acc[p]);
        }
        float* out = g_h4 + (size_t)(b * NC + ci) * KNN * 128;
#pragma unroll
        for (int p = 0; p < 32; p++) out[p * 128 + t] = fmaxf(acc[p], 0.0f);
    }
}

// ===========================================================================
// K3b: conv5 (128 -> 1024) + relu + per-position max folded locally, then one
// atomicMax(fp-bits) per (b, oc). Grid z = 8 tiles of 128 output channels.
// ===========================================================================
__global__ __launch_bounds__(128) void k_conv5(const float* __restrict__ w5,
                                               const float* __restrict__ b5) {
    const int ci = blockIdx.x, b = blockIdx.y, z = blockIdx.z;
    if (ci >= g_cnt[b]) return;
    const int t = threadIdx.x;

    __shared__ float H[32 * 128];
    const float* h4 = g_h4 + (size_t)(b * NC + ci) * KNN * 128;
    for (int i = t; i < 32 * 128; i += 128) H[i] = h4[i];
    __syncthreads();

    const int oc = z * 128 + t;
    float acc[32];
#pragma unroll
    for (int p = 0; p < 32; p++) acc[p] = 0.0f;
    const float* wr = w5 + (size_t)oc * 128;
#pragma unroll 4
    for (int j = 0; j < 128; j++) {
        float w = __ldg(wr + j);
#pragma unroll
        for (int p = 0; p < 32; p++) acc[p] = fmaf(w, H[p * 128 + j], acc[p]);
    }
    float m = acc[0];
#pragma unroll
    for (int p = 1; p < 32; p++) m = fmaxf(m, acc[p]);
    m = fmaxf(m + __ldg(b5 + oc), 0.0f);   // relu(max+bias) == max(relu(+bias))
    atomicMax(&g_pool[b * 1024 + oc], __float_as_int(m));
}

// ===========================================================================
// K4: FC head. One block (512 thr) per batch.
// ===========================================================================
__global__ __launch_bounds__(512) void k_fc(
    const float* __restrict__ fw1, const float* __restrict__ fb1,
    const float* __restrict__ fw2, const float* __restrict__ fb2,
    const float* __restrict__ fw3, const float* __restrict__ fb3,
    float* __restrict__ out) {
    const int b = blockIdx.x;
    const int t = threadIdx.x;
    __shared__ float G[1024];
    __shared__ float A1[512];
    __shared__ float A2[256];

    G[t]       = __int_as_float(g_pool[b * 1024 + t]);
    G[t + 512] = __int_as_float(g_pool[b * 1024 + 512 + t]);
    __syncthreads();

    {
        float acc = __ldg(fb1 + t);
        const float* wr = fw1 + (size_t)t * 1024;
#pragma unroll 4
        for (int i = 0; i < 1024; i++) acc = fmaf(__ldg(wr + i), G[i], acc);
        A1[t] = fmaxf(acc, 0.0f);
    }
    __syncthreads();
    if (t < 256) {
        float acc = __ldg(fb2 + t);
        const float* wr = fw2 + (size_t)t * 512;
#pragma unroll 4
        for (int i = 0; i < 512; i++) acc = fmaf(__ldg(wr + i), A1[i], acc);
        A2[t] = fmaxf(acc, 0.0f);
    }
    __syncthreads();
    if (t < 3) {
        float acc = __ldg(fb3 + t);
        const float* wr = fw3 + (size_t)t * 256;
#pragma unroll 4
        for (int i = 0; i < 256; i++) acc = fmaf(__ldg(wr + i), A2[i], acc);
        out[b * 3 + t] = acc;
    }
}

// ===========================================================================
extern "C" void kernel_launch(void* const* d_in, const int* in_sizes, int n_in,
                              void* d_out, int out_size) {
    const float* x    = (const float*)d_in[0];
    const int*   far0 = (const int*)d_in[1];
    const float* w1 = (const float*)d_in[2];  const float* b1 = (const float*)d_in[3];
    const float* w2 = (const float*)d_in[4];  const float* b2 = (const float*)d_in[5];
    const float* w3 = (const float*)d_in[6];  const float* b3 = (const float*)d_in[7];
    const float* w4 = (const float*)d_in[8];  const float* b4 = (const float*)d_in[9];
    const float* w5 = (const float*)d_in[10]; const float* b5 = (const float*)d_in[11];
    const float* fw1 = (const float*)d_in[12]; const float* fb1 = (const float*)d_in[13];
    const float* fw2 = (const float*)d_in[14]; const float* fb2 = (const float*)d_in[15];
    const float* fw3 = (const float*)d_in[16]; const float* fb3 = (const float*)d_in[17];
    float* out = (float*)d_out;

    k_fps<<<NB, 512>>>(x, far0);
    k_knn<<<dim3(NC, NB), 256>>>(x);
    k_conv14<<<dim3(NC, NB), 128>>>(w1, b1, w2, b2, w3, b3, w4, b4);
    k_conv5<<<dim3(NC, NB, 8), 128>>>(w5, b5);
    k_fc<<<NB, 512>>>(fw1, fb1, fw2, fb2, fw3, fb3, out);
}

// round 4
// speedup vs baseline: 1.8707x; 1.8707x over previous
#include <cuda_runtime.h>
#include <cuda_bf16.h>
#include <cstdint>

// ---------------------------------------------------------------------------
// cls_model: FPS (cycle-collapsed) -> [KNN(32) + conv1..4 fused] -> conv5+pool
//            -> MLP head.   B=4, N=16384, C=3, N_C=1024, K=32
// R3: compact data-shaped grids (blocks loop ci += stride after reading g_cnt),
//     KNN+conv1-4 fused into one 512-thread kernel, float4 FC head.
// ---------------------------------------------------------------------------

#define NB 4
#define NPTS 16384
#define NC 1024
#define KNN 32

#define FUSED_GRID_X 128
#define CONV5_GRID_X 64

// ---- device scratch (no allocations allowed) ----
__device__ int   g_cnt[NB];                         // distinct centroid count per batch
__device__ float g_cent[NB * NC * 3];               // distinct centroid coords
__device__ float g_h4[(size_t)NB * NC * KNN * 128]; // conv4 activations
__device__ int   g_pool[NB * 1024];                 // maxpool accumulator (float bits, >=0)

static __device__ __forceinline__ float f_inf() { return __int_as_float(0x7f800000); }

// ===========================================================================
// K1: FPS with cycle detection. One block per batch, 512 threads, 32 pts/thread
// in registers. Also zeroes g_pool.
// Exact arithmetic: d = ((dx*dx + dy*dy) + dz*dz), no FMA contraction,
// argmax tie -> lowest index (matches jnp.argmax).
// ===========================================================================
__global__ __launch_bounds__(512) void k_fps(const float* __restrict__ x,
                                             const int* __restrict__ far0) {
    const int b = blockIdx.x;
    const int t = threadIdx.x;
    const float* xb = x + (size_t)b * NPTS * 3;

    float px[32], py[32], pz[32];
#pragma unroll
    for (int i = 0; i < 32; i++) {
        int n = i * 512 + t;
        px[i] = xb[n * 3 + 0];
        py[i] = xb[n * 3 + 1];
        pz[i] = xb[n * 3 + 2];
    }

    __shared__ unsigned seen[512];
    __shared__ float cc[3];
    __shared__ float rd[16]; __shared__ int rn[16];
    __shared__ float rx[16], ry[16], rz[16];
    __shared__ int sdone;

    // reset pool for this launch (graph replays reuse device globals)
    g_pool[b * 1024 + t] = 0;
    g_pool[b * 1024 + 512 + t] = 0;
    seen[t] = 0u;
    __syncthreads();

    if (t == 0) {
        int f = far0[b];
        seen[f >> 5] = 1u << (f & 31);
        float cx = xb[f * 3 + 0], cy = xb[f * 3 + 1], cz = xb[f * 3 + 2];
        cc[0] = cx; cc[1] = cy; cc[2] = cz;
        g_cent[(b * NC + 0) * 3 + 0] = cx;
        g_cent[(b * NC + 0) * 3 + 1] = cy;
        g_cent[(b * NC + 0) * 3 + 2] = cz;
        sdone = 0;
    }
    __syncthreads();

    int cnt = 1;
    for (int it = 1; it < NC; it++) {
        float cx = cc[0], cy = cc[1], cz = cc[2];
        float best = -1.0f; int bn = 0;
        float bx = 0.f, by = 0.f, bz = 0.f;
#pragma unroll
        for (int i = 0; i < 32; i++) {
            float dx = __fsub_rn(px[i], cx);
            float dy = __fsub_rn(py[i], cy);
            float dz = __fsub_rn(pz[i], cz);
            float d = __fadd_rn(__fadd_rn(__fmul_rn(dx, dx), __fmul_rn(dy, dy)),
                                __fmul_rn(dz, dz));
            int n = i * 512 + t;
            if (d > best) { best = d; bn = n; bx = px[i]; by = py[i]; bz = pz[i]; }
        }
#pragma unroll
        for (int o = 16; o > 0; o >>= 1) {
            float od = __shfl_down_sync(0xffffffffu, best, o);
            int   on = __shfl_down_sync(0xffffffffu, bn,   o);
            float ox = __shfl_down_sync(0xffffffffu, bx,   o);
            float oy = __shfl_down_sync(0xffffffffu, by,   o);
            float oz = __shfl_down_sync(0xffffffffu, bz,   o);
            if (od > best || (od == best && on < bn)) {
                best = od; bn = on; bx = ox; by = oy; bz = oz;
            }
        }
        int w = t >> 5;
        if ((t & 31) == 0) { rd[w] = best; rn[w] = bn; rx[w] = bx; ry[w] = by; rz[w] = bz; }
        __syncthreads();
        if (t == 0) {
            best = rd[0]; bn = rn[0]; bx = rx[0]; by = ry[0]; bz = rz[0];
            for (int j = 1; j < 16; j++) {
                if (rd[j] > best || (rd[j] == best && rn[j] < bn)) {
                    best = rd[j]; bn = rn[j]; bx = rx[j]; by = ry[j]; bz = rz[j];
                }
            }
            unsigned bit = 1u << (bn & 31);
            if (seen[bn >> 5] & bit) {
                sdone = 1;             // cycle: all future centroids are repeats
            } else {
                seen[bn >> 5] |= bit;
                g_cent[(b * NC + cnt) * 3 + 0] = bx;
                g_cent[(b * NC + cnt) * 3 + 1] = by;
                g_cent[(b * NC + cnt) * 3 + 2] = bz;
                cc[0] = bx; cc[1] = by; cc[2] = bz;
            }
        }
        __syncthreads();
        if (sdone) break;
        cnt++;
    }
    if (t == 0) g_cnt[b] = cnt;
}

// ===========================================================================
// K2: fused KNN(32) + conv1..conv4 per distinct centroid. 512 threads.
// Compact grid: block loops ci += FUSED_GRID_X while ci < g_cnt[b].
// KNN: d2 in registers (32/thread); 32 iterative lex-min rounds; d2 formula
// matches reference exactly: (c2 + x2) - 2*dot, each op rounded, tie->low idx.
// Convs: smem-staged activations, conv4 written coalesced to g_h4.
// ===========================================================================
__global__ __launch_bounds__(512) void k_fused(
    const float* __restrict__ x,
    const float* __restrict__ w1, const float* __restrict__ b1,
    const float* __restrict__ w2, const float* __restrict__ b2,
    const float* __restrict__ w3, const float* __restrict__ b3,
    const float* __restrict__ w4, const float* __restrict__ b4) {
    const int b = blockIdx.y;
    const int cnt = g_cnt[b];
    const int t = threadIdx.x;
    const float* xb = x + (size_t)b * NPTS * 3;

    __shared__ float sd[16]; __shared__ int sn[16];
    __shared__ int s_w;
    __shared__ int wlist[KNN];
    __shared__ float P[KNN][4];
    __shared__ float Ha[KNN][65];
    __shared__ float Hb[KNN][65];

    for (int ci = blockIdx.x; ci < cnt; ci += FUSED_GRID_X) {
        // ---------------- KNN phase ----------------
        const float cx = g_cent[(b * NC + ci) * 3 + 0];
        const float cy = g_cent[(b * NC + ci) * 3 + 1];
        const float cz = g_cent[(b * NC + ci) * 3 + 2];
        const float c2 = __fadd_rn(__fadd_rn(__fmul_rn(cx, cx), __fmul_rn(cy, cy)),
                                   __fmul_rn(cz, cz));

        float d[32];
#pragma unroll
        for (int i = 0; i < 32; i++) {
            int n = i * 512 + t;
            float X = xb[n * 3 + 0], Y = xb[n * 3 + 1], Z = xb[n * 3 + 2];
            float x2 = __fadd_rn(__fadd_rn(__fmul_rn(X, X), __fmul_rn(Y, Y)),
                                 __fmul_rn(Z, Z));
            float dt = __fadd_rn(__fadd_rn(__fmul_rn(cx, X), __fmul_rn(cy, Y)),
                                 __fmul_rn(cz, Z));
            d[i] = __fsub_rn(__fadd_rn(c2, x2), __fmul_rn(2.0f, dt));
        }

        for (int r = 0; r < KNN; r++) {
            float best = f_inf(); int bn = 1 << 30;
#pragma unroll
            for (int i = 0; i < 32; i++) {
                int n = i * 512 + t;
                if (d[i] < best || (d[i] == best && n < bn)) { best = d[i]; bn = n; }
            }
#pragma unroll
            for (int o = 16; o > 0; o >>= 1) {
                float od = __shfl_down_sync(0xffffffffu, best, o);
                int   on = __shfl_down_sync(0xffffffffu, bn,   o);
                if (od < best || (od == best && on < bn)) { best = od; bn = on; }
            }
            int w = t >> 5;
            if ((t & 31) == 0) { sd[w] = best; sn[w] = bn; }
            __syncthreads();
            if (t == 0) {
                best = sd[0]; bn = sn[0];
                for (int j = 1; j < 16; j++)
                    if (sd[j] < best || (sd[j] == best && sn[j] < bn)) { best = sd[j]; bn = sn[j]; }
                s_w = bn;
                wlist[r] = bn;
            }
            __syncthreads();
            int wn = s_w;
#pragma unroll
            for (int i = 0; i < 32; i++)
                if ((i << 9) + t == wn) d[i] = f_inf();
        }
        __syncthreads();

        // gather neighbor coords
        if (t < KNN) {
            int n = wlist[t];
            P[t][0] = xb[n * 3 + 0];
            P[t][1] = xb[n * 3 + 1];
            P[t][2] = xb[n * 3 + 2];
        }
        __syncthreads();

        // ---------------- conv1: 3 -> 64 (P -> Ha) ----------------
        {
            // 2048 outputs, 4/thread: ch = t & 63 (fixed), p = (t>>6) + 8k
            int ch = t & 63, p0 = t >> 6;
            float wa = __ldg(w1 + ch * 3 + 0), wb = __ldg(w1 + ch * 3 + 1),
                  wc = __ldg(w1 + ch * 3 + 2), bb = __ldg(b1 + ch);
#pragma unroll
            for (int k = 0; k < 4; k++) {
                int p = p0 + 8 * k;
                float v = fmaf(wa, P[p][0], fmaf(wb, P[p][1], fmaf(wc, P[p][2], bb)));
                Ha[p][ch] = fmaxf(v, 0.0f);
            }
        }
        __syncthreads();

        // ---------------- conv2: 64 -> 64 (Ha -> Hb) ----------------
        {
            int ch = t & 63, p0 = t >> 6;
            float bb = __ldg(b2 + ch);
            float a0 = bb, a1 = bb, a2 = bb, a3 = bb;
            const float* wr = w2 + ch * 64;
#pragma unroll 8
            for (int j = 0; j < 64; j++) {
                float w = __ldg(wr + j);
                a0 = fmaf(w, Ha[p0 +  0][j], a0);
                a1 = fmaf(w, Ha[p0 +  8][j], a1);
                a2 = fmaf(w, Ha[p0 + 16][j], a2);
                a3 = fmaf(w, Ha[p0 + 24][j], a3);
            }
            Hb[p0 +  0][ch] = fmaxf(a0, 0.0f);
            Hb[p0 +  8][ch] = fmaxf(a1, 0.0f);
            Hb[p0 + 16][ch] = fmaxf(a2, 0.0f);
            Hb[p0 + 24][ch] = fmaxf(a3, 0.0f);
        }
        __syncthreads();

        // ---------------- conv3: 64 -> 64 (Hb -> Ha) ----------------
        {
            int ch = t & 63, p0 = t >> 6;
            float bb = __ldg(b3 + ch);
            float a0 = bb, a1 = bb, a2 = bb, a3 = bb;
            const float* wr = w3 + ch * 64;
#pragma unroll 8
            for (int j = 0; j < 64; j++) {
                float w = __ldg(wr + j);
                a0 = fmaf(w, Hb[p0 +  0][j], a0);
                a1 = fmaf(w, Hb[p0 +  8][j], a1);
                a2 = fmaf(w, Hb[p0 + 16][j], a2);
                a3 = fmaf(w, Hb[p0 + 24][j], a3);
            }
            Ha[p0 +  0][ch] = fmaxf(a0, 0.0f);
            Ha[p0 +  8][ch] = fmaxf(a1, 0.0f);
            Ha[p0 + 16][ch] = fmaxf(a2, 0.0f);
            Ha[p0 + 24][ch] = fmaxf(a3, 0.0f);
        }
        __syncthreads();

        // ---------------- conv4: 64 -> 128 (Ha -> g_h4, coalesced) ----------
        {
            // 4096 outputs, 8/thread: oc = t & 127 (fixed), p = (t>>7) + 4k
            int oc = t & 127, p0 = t >> 7;
            float bb = __ldg(b4 + oc);
            float acc[8];
#pragma unroll
            for (int k = 0; k < 8; k++) acc[k] = bb;
            const float* wr = w4 + oc * 64;
#pragma unroll 4
            for (int j = 0; j < 64; j++) {
                float w = __ldg(wr + j);
#pragma unroll
                for (int k = 0; k < 8; k++)
                    acc[k] = fmaf(w, Ha[p0 + 4 * k][j], acc[k]);
            }
            float* out = g_h4 + (size_t)(b * NC + ci) * KNN * 128;
#pragma unroll
            for (int k = 0; k < 8; k++)
                out[(p0 + 4 * k) * 128 + oc] = fmaxf(acc[k], 0.0f);
        }
        __syncthreads();   // protect smem reuse on next ci iteration
    }
}

// ===========================================================================
// K3: conv5 (128 -> 1024) + relu + per-position max folded locally, then one
// atomicMax(fp-bits) per (b, oc). Compact grid: block loops over work items
// w = ci*8 + z  (z = 128-channel tile).
// ===========================================================================
__global__ __launch_bounds__(128) void k_conv5(const float* __restrict__ w5,
                                               const float* __restrict__ b5) {
    const int b = blockIdx.y;
    const int cnt = g_cnt[b];
    const int nwork = cnt * 8;
    const int t = threadIdx.x;

    __shared__ float H[32 * 128];

    for (int wkr = blockIdx.x; wkr < nwork; wkr += CONV5_GRID_X) {
        const int ci = wkr >> 3, z = wkr & 7;
        const float* h4 = g_h4 + (size_t)(b * NC + ci) * KNN * 128;
        for (int i = t; i < 32 * 128; i += 128) H[i] = h4[i];
        __syncthreads();

        const int oc = z * 128 + t;
        float acc[32];
#pragma unroll
        for (int p = 0; p < 32; p++) acc[p] = 0.0f;
        const float* wr = w5 + (size_t)oc * 128;
#pragma unroll 4
        for (int j = 0; j < 128; j++) {
            float w = __ldg(wr + j);
#pragma unroll
            for (int p = 0; p < 32; p++) acc[p] = fmaf(w, H[p * 128 + j], acc[p]);
        }
        float m = acc[0];
#pragma unroll
        for (int p = 1; p < 32; p++) m = fmaxf(m, acc[p]);
        m = fmaxf(m + __ldg(b5 + oc), 0.0f);   // relu(max+bias) == max(relu(+bias))
        atomicMax(&g_pool[b * 1024 + oc], __float_as_int(m));
        __syncthreads();   // protect H reuse on next work item
    }
}

// ===========================================================================
// K4: FC head. One block (512 thr) per batch; float4 weight loads.
// ===========================================================================
__global__ __launch_bounds__(512) void k_fc(
    const float* __restrict__ fw1, const float* __restrict__ fb1,
    const float* __restrict__ fw2, const float* __restrict__ fb2,
    const float* __restrict__ fw3, const float* __restrict__ fb3,
    float* __restrict__ out) {
    const int b = blockIdx.x;
    const int t = threadIdx.x;
    __shared__ float G[1024];
    __shared__ float A1[512];
    __shared__ float A2[256];

    G[t]       = __int_as_float(g_pool[b * 1024 + t]);
    G[t + 512] = __int_as_float(g_pool[b * 1024 + 512 + t]);
    __syncthreads();

    {
        const float4* wr = (const float4*)(fw1 + (size_t)t * 1024);
        float a0 = 0.f, a1 = 0.f, a2 = 0.f, a3 = 0.f;
#pragma unroll 8
        for (int i = 0; i < 256; i++) {
            float4 w = __ldg(wr + i);
            a0 = fmaf(w.x, G[4 * i + 0], a0);
            a1 = fmaf(w.y, G[4 * i + 1], a1);
            a2 = fmaf(w.z, G[4 * i + 2], a2);
            a3 = fmaf(w.w, G[4 * i + 3], a3);
        }
        A1[t] = fmaxf(((a0 + a1) + (a2 + a3)) + __ldg(fb1 + t), 0.0f);
    }
    __syncthreads();
    if (t < 256) {
        const float4* wr = (const float4*)(fw2 + (size_t)t * 512);
        float a0 = 0.f, a1 = 0.f, a2 = 0.f, a3 = 0.f;
#pragma unroll 8
        for (int i = 0; i < 128; i++) {
            float4 w = __ldg(wr + i);
            a0 = fmaf(w.x, A1[4 * i + 0], a0);
            a1 = fmaf(w.y, A1[4 * i + 1], a1);
            a2 = fmaf(w.z, A1[4 * i + 2], a2);
            a3 = fmaf(w.w, A1[4 * i + 3], a3);
        }
        A2[t] = fmaxf(((a0 + a1) + (a2 + a3)) + __ldg(fb2 + t), 0.0f);
    }
    __syncthreads();
    if (t < 3) {
        const float4* wr = (const float4*)(fw3 + (size_t)t * 256);
        float a0 = 0.f, a1 = 0.f, a2 = 0.f, a3 = 0.f;
#pragma unroll 8
        for (int i = 0; i < 64; i++) {
            float4 w = __ldg(wr + i);
            a0 = fmaf(w.x, A2[4 * i + 0], a0);
            a1 = fmaf(w.y, A2[4 * i + 1], a1);
            a2 = fmaf(w.z, A2[4 * i + 2], a2);
            a3 = fmaf(w.w, A2[4 * i + 3], a3);
        }
        out[b * 3 + t] = ((a0 + a1) + (a2 + a3)) + __ldg(fb3 + t);
    }
}

// ===========================================================================
extern "C" void kernel_launch(void* const* d_in, const int* in_sizes, int n_in,
                              void* d_out, int out_size) {
    const float* x    = (const float*)d_in[0];
    const int*   far0 = (const int*)d_in[1];
    const float* w1 = (const float*)d_in[2];  const float* b1 = (const float*)d_in[3];
    const float* w2 = (const float*)d_in[4];  const float* b2 = (const float*)d_in[5];
    const float* w3 = (const float*)d_in[6];  const float* b3 = (const float*)d_in[7];
    const float* w4 = (const float*)d_in[8];  const float* b4 = (const float*)d_in[9];
    const float* w5 = (const float*)d_in[10]; const float* b5 = (const float*)d_in[11];
    const float* fw1 = (const float*)d_in[12]; const float* fb1 = (const float*)d_in[13];
    const float* fw2 = (const float*)d_in[14]; const float* fb2 = (const float*)d_in[15];
    const float* fw3 = (const float*)d_in[16]; const float* fb3 = (const float*)d_in[17];
    float* out = (float*)d_out;

    k_fps<<<NB, 512>>>(x, far0);
    k_fused<<<dim3(FUSED_GRID_X, NB), 512>>>(x, w1, b1, w2, b2, w3, b3, w4, b4);
    k_conv5<<<dim3(CONV5_GRID_X, NB), 128>>>(w5, b5);
    k_fc<<<NB, 512>>>(fw1, fb1, fw2, fb2, fw3, fb3, out);
}

// round 5
// speedup vs baseline: 2.7771x; 1.4845x over previous
#include <cuda_runtime.h>
#include <cuda_bf16.h>
#include <cstdint>

// ---------------------------------------------------------------------------
// cls_model: FPS (cycle-collapsed) -> [KNN(32)+conv1..4 fused] -> conv5+pool
//            -> parallel FC head.   B=4, N=16384, C=3, N_C=1024, K=32
// R4: FC head parallelized across the chip (one block per output neuron);
//     L2 warm-up for FC/conv5 weights overlapped under k_fps.
// ---------------------------------------------------------------------------

#define NB 4
#define NPTS 16384
#define NC 1024
#define KNN 32

#define FUSED_GRID_X 128
#define CONV5_GRID_X 64
#define WARM_BLOCKS 64

// ---- device scratch (no allocations allowed) ----
__device__ int   g_cnt[NB];
__device__ float g_cent[NB * NC * 3];
__device__ float g_h4[(size_t)NB * NC * KNN * 128];
__device__ int   g_pool[NB * 1024];     // maxpool accumulator (float bits, >=0)
__device__ float g_a1[NB * 512];
__device__ float g_a2[NB * 256];
__device__ float g_sink[WARM_BLOCKS];   // keeps warm-up loads alive

static __device__ __forceinline__ float f_inf() { return __int_as_float(0x7f800000); }

// ===========================================================================
// K1: FPS with cycle detection (blocks 0..NB-1) + L2 warm-up for FC/conv5
// weights (blocks NB..NB+WARM_BLOCKS-1, running concurrently on idle SMs).
// FPS arithmetic bit-exact vs reference; argmax tie -> lowest index.
// ===========================================================================
__global__ __launch_bounds__(512) void k_fps(const float* __restrict__ x,
                                             const int* __restrict__ far0,
                                             const float* __restrict__ fw1,
                                             const float* __restrict__ fw2,
                                             const float* __restrict__ w5) {
    const int t = threadIdx.x;

    if (blockIdx.x >= NB) {
        // ---- warm-up block: stream weights into L2, keep them live ----
        const int wb = blockIdx.x - NB;
        float s = 0.0f;
        // fw1: 512*1024 floats = 128K float4
        const float4* p1 = (const float4*)fw1;
        for (int i = wb * 512 + t; i < 512 * 256; i += WARM_BLOCKS * 512) {
            float4 v = __ldg(p1 + i); s += v.x + v.y + v.z + v.w;
        }
        // fw2: 256*512 floats = 32K float4
        const float4* p2 = (const float4*)fw2;
        for (int i = wb * 512 + t; i < 256 * 128; i += WARM_BLOCKS * 512) {
            float4 v = __ldg(p2 + i); s += v.x + v.y + v.z + v.w;
        }
        // w5: 1024*128 floats = 32K float4
        const float4* p5 = (const float4*)w5;
        for (int i = wb * 512 + t; i < 1024 * 32; i += WARM_BLOCKS * 512) {
            float4 v = __ldg(p5 + i); s += v.x + v.y + v.z + v.w;
        }
        if (s == -1.2345678e38f && t == 0) g_sink[wb] = s;  // never true; defeats DCE
        return;
    }

    const int b = blockIdx.x;
    const float* xb = x + (size_t)b * NPTS * 3;

    float px[32], py[32], pz[32];
#pragma unroll
    for (int i = 0; i < 32; i++) {
        int n = i * 512 + t;
        px[i] = xb[n * 3 + 0];
        py[i] = xb[n * 3 + 1];
        pz[i] = xb[n * 3 + 2];
    }

    __shared__ unsigned seen[512];
    __shared__ float cc[3];
    __shared__ float rd[16]; __shared__ int rn[16];
    __shared__ float rx[16], ry[16], rz[16];
    __shared__ int sdone;

    g_pool[b * 1024 + t] = 0;
    g_pool[b * 1024 + 512 + t] = 0;
    seen[t] = 0u;
    __syncthreads();

    if (t == 0) {
        int f = far0[b];
        seen[f >> 5] = 1u << (f & 31);
        float cx = xb[f * 3 + 0], cy = xb[f * 3 + 1], cz = xb[f * 3 + 2];
        cc[0] = cx; cc[1] = cy; cc[2] = cz;
        g_cent[(b * NC + 0) * 3 + 0] = cx;
        g_cent[(b * NC + 0) * 3 + 1] = cy;
        g_cent[(b * NC + 0) * 3 + 2] = cz;
        sdone = 0;
    }
    __syncthreads();

    int cnt = 1;
    for (int it = 1; it < NC; it++) {
        float cx = cc[0], cy = cc[1], cz = cc[2];
        float best = -1.0f; int bn = 0;
        float bx = 0.f, by = 0.f, bz = 0.f;
#pragma unroll
        for (int i = 0; i < 32; i++) {
            float dx = __fsub_rn(px[i], cx);
            float dy = __fsub_rn(py[i], cy);
            float dz = __fsub_rn(pz[i], cz);
            float d = __fadd_rn(__fadd_rn(__fmul_rn(dx, dx), __fmul_rn(dy, dy)),
                                __fmul_rn(dz, dz));
            int n = i * 512 + t;
            if (d > best) { best = d; bn = n; bx = px[i]; by = py[i]; bz = pz[i]; }
        }
#pragma unroll
        for (int o = 16; o > 0; o >>= 1) {
            float od = __shfl_down_sync(0xffffffffu, best, o);
            int   on = __shfl_down_sync(0xffffffffu, bn,   o);
            float ox = __shfl_down_sync(0xffffffffu, bx,   o);
            float oy = __shfl_down_sync(0xffffffffu, by,   o);
            float oz = __shfl_down_sync(0xffffffffu, bz,   o);
            if (od > best || (od == best && on < bn)) {
                best = od; bn = on; bx = ox; by = oy; bz = oz;
            }
        }
        int w = t >> 5;
        if ((t & 31) == 0) { rd[w] = best; rn[w] = bn; rx[w] = bx; ry[w] = by; rz[w] = bz; }
        __syncthreads();
        if (t == 0) {
            best = rd[0]; bn = rn[0]; bx = rx[0]; by = ry[0]; bz = rz[0];
            for (int j = 1; j < 16; j++) {
                if (rd[j] > best || (rd[j] == best && rn[j] < bn)) {
                    best = rd[j]; bn = rn[j]; bx = rx[j]; by = ry[j]; bz = rz[j];
                }
            }
            unsigned bit = 1u << (bn & 31);
            if (seen[bn >> 5] & bit) {
                sdone = 1;
            } else {
                seen[bn >> 5] |= bit;
                g_cent[(b * NC + cnt) * 3 + 0] = bx;
                g_cent[(b * NC + cnt) * 3 + 1] = by;
                g_cent[(b * NC + cnt) * 3 + 2] = bz;
                cc[0] = bx; cc[1] = by; cc[2] = bz;
            }
        }
        __syncthreads();
        if (sdone) break;
        cnt++;
    }
    if (t == 0) g_cnt[b] = cnt;
}

// ===========================================================================
// K2: fused KNN(32) + conv1..conv4 per distinct centroid. 512 threads.
// Compact grid with ci-loop. KNN d2 formula bit-exact vs reference.
// ===========================================================================
__global__ __launch_bounds__(512) void k_fused(
    const float* __restrict__ x,
    const float* __restrict__ w1, const float* __restrict__ b1,
    const float* __restrict__ w2, const float* __restrict__ b2,
    const float* __restrict__ w3, const float* __restrict__ b3,
    const float* __restrict__ w4, const float* __restrict__ b4) {
    const int b = blockIdx.y;
    const int cnt = g_cnt[b];
    const int t = threadIdx.x;
    const float* xb = x + (size_t)b * NPTS * 3;

    __shared__ float sd[16]; __shared__ int sn[16];
    __shared__ int s_w;
    __shared__ int wlist[KNN];
    __shared__ float P[KNN][4];
    __shared__ float Ha[KNN][65];
    __shared__ float Hb[KNN][65];

    for (int ci = blockIdx.x; ci < cnt; ci += FUSED_GRID_X) {
        const float cx = g_cent[(b * NC + ci) * 3 + 0];
        const float cy = g_cent[(b * NC + ci) * 3 + 1];
        const float cz = g_cent[(b * NC + ci) * 3 + 2];
        const float c2 = __fadd_rn(__fadd_rn(__fmul_rn(cx, cx), __fmul_rn(cy, cy)),
                                   __fmul_rn(cz, cz));

        float d[32];
#pragma unroll
        for (int i = 0; i < 32; i++) {
            int n = i * 512 + t;
            float X = xb[n * 3 + 0], Y = xb[n * 3 + 1], Z = xb[n * 3 + 2];
            float x2 = __fadd_rn(__fadd_rn(__fmul_rn(X, X), __fmul_rn(Y, Y)),
                                 __fmul_rn(Z, Z));
            float dt = __fadd_rn(__fadd_rn(__fmul_rn(cx, X), __fmul_rn(cy, Y)),
                                 __fmul_rn(cz, Z));
            d[i] = __fsub_rn(__fadd_rn(c2, x2), __fmul_rn(2.0f, dt));
        }

        for (int r = 0; r < KNN; r++) {
            float best = f_inf(); int bn = 1 << 30;
#pragma unroll
            for (int i = 0; i < 32; i++) {
                int n = i * 512 + t;
                if (d[i] < best || (d[i] == best && n < bn)) { best = d[i]; bn = n; }
            }
#pragma unroll
            for (int o = 16; o > 0; o >>= 1) {
                float od = __shfl_down_sync(0xffffffffu, best, o);
                int   on = __shfl_down_sync(0xffffffffu, bn,   o);
                if (od < best || (od == best && on < bn)) { best = od; bn = on; }
            }
            int w = t >> 5;
            if ((t & 31) == 0) { sd[w] = best; sn[w] = bn; }
            __syncthreads();
            if (t == 0) {
                best = sd[0]; bn = sn[0];
                for (int j = 1; j < 16; j++)
                    if (sd[j] < best || (sd[j] == best && sn[j] < bn)) { best = sd[j]; bn = sn[j]; }
                s_w = bn;
                wlist[r] = bn;
            }
            __syncthreads();
            int wn = s_w;
#pragma unroll
            for (int i = 0; i < 32; i++)
                if ((i << 9) + t == wn) d[i] = f_inf();
        }
        __syncthreads();

        if (t < KNN) {
            int n = wlist[t];
            P[t][0] = xb[n * 3 + 0];
            P[t][1] = xb[n * 3 + 1];
            P[t][2] = xb[n * 3 + 2];
        }
        __syncthreads();

        // conv1: 3 -> 64
        {
            int ch = t & 63, p0 = t >> 6;
            float wa = __ldg(w1 + ch * 3 + 0), wb = __ldg(w1 + ch * 3 + 1),
                  wc = __ldg(w1 + ch * 3 + 2), bb = __ldg(b1 + ch);
#pragma unroll
            for (int k = 0; k < 4; k++) {
                int p = p0 + 8 * k;
                float v = fmaf(wa, P[p][0], fmaf(wb, P[p][1], fmaf(wc, P[p][2], bb)));
                Ha[p][ch] = fmaxf(v, 0.0f);
            }
        }
        __syncthreads();

        // conv2: 64 -> 64 (Ha -> Hb)
        {
            int ch = t & 63, p0 = t >> 6;
            float bb = __ldg(b2 + ch);
            float a0 = bb, a1 = bb, a2 = bb, a3 = bb;
            const float* wr = w2 + ch * 64;
#pragma unroll 8
            for (int j = 0; j < 64; j++) {
                float w = __ldg(wr + j);
                a0 = fmaf(w, Ha[p0 +  0][j], a0);
                a1 = fmaf(w, Ha[p0 +  8][j], a1);
                a2 = fmaf(w, Ha[p0 + 16][j], a2);
                a3 = fmaf(w, Ha[p0 + 24][j], a3);
            }
            Hb[p0 +  0][ch] = fmaxf(a0, 0.0f);
            Hb[p0 +  8][ch] = fmaxf(a1, 0.0f);
            Hb[p0 + 16][ch] = fmaxf(a2, 0.0f);
            Hb[p0 + 24][ch] = fmaxf(a3, 0.0f);
        }
        __syncthreads();

        // conv3: 64 -> 64 (Hb -> Ha)
        {
            int ch = t & 63, p0 = t >> 6;
            float bb = __ldg(b3 + ch);
            float a0 = bb, a1 = bb, a2 = bb, a3 = bb;
            const float* wr = w3 + ch * 64;
#pragma unroll 8
            for (int j = 0; j < 64; j++) {
                float w = __ldg(wr + j);
                a0 = fmaf(w, Hb[p0 +  0][j], a0);
                a1 = fmaf(w, Hb[p0 +  8][j], a1);
                a2 = fmaf(w, Hb[p0 + 16][j], a2);
                a3 = fmaf(w, Hb[p0 + 24][j], a3);
            }
            Ha[p0 +  0][ch] = fmaxf(a0, 0.0f);
            Ha[p0 +  8][ch] = fmaxf(a1, 0.0f);
            Ha[p0 + 16][ch] = fmaxf(a2, 0.0f);
            Ha[p0 + 24][ch] = fmaxf(a3, 0.0f);
        }
        __syncthreads();

        // conv4: 64 -> 128 (Ha -> g_h4, coalesced)
        {
            int oc = t & 127, p0 = t >> 7;
            float bb = __ldg(b4 + oc);
            float acc[8];
#pragma unroll
            for (int k = 0; k < 8; k++) acc[k] = bb;
            const float* wr = w4 + oc * 64;
#pragma unroll 4
            for (int j = 0; j < 64; j++) {
                float w = __ldg(wr + j);
#pragma unroll
                for (int k = 0; k < 8; k++)
                    acc[k] = fmaf(w, Ha[p0 + 4 * k][j], acc[k]);
            }
            float* out = g_h4 + (size_t)(b * NC + ci) * KNN * 128;
#pragma unroll
            for (int k = 0; k < 8; k++)
                out[(p0 + 4 * k) * 128 + oc] = fmaxf(acc[k], 0.0f);
        }
        __syncthreads();
    }
}

// ===========================================================================
// K3: conv5 (128->1024) + relu + local position-max, atomicMax into g_pool.
// ===========================================================================
__global__ __launch_bounds__(128) void k_conv5(const float* __restrict__ w5,
                                               const float* __restrict__ b5) {
    const int b = blockIdx.y;
    const int cnt = g_cnt[b];
    const int nwork = cnt * 8;
    const int t = threadIdx.x;

    __shared__ float H[32 * 128];

    for (int wkr = blockIdx.x; wkr < nwork; wkr += CONV5_GRID_X) {
        const int ci = wkr >> 3, z = wkr & 7;
        const float* h4 = g_h4 + (size_t)(b * NC + ci) * KNN * 128;
        for (int i = t; i < 32 * 128; i += 128) H[i] = h4[i];
        __syncthreads();

        const int oc = z * 128 + t;
        float acc[32];
#pragma unroll
        for (int p = 0; p < 32; p++) acc[p] = 0.0f;
        const float* wr = w5 + (size_t)oc * 128;
#pragma unroll 4
        for (int j = 0; j < 128; j++) {
            float w = __ldg(wr + j);
#pragma unroll
            for (int p = 0; p < 32; p++) acc[p] = fmaf(w, H[p * 128 + j], acc[p]);
        }
        float m = acc[0];
#pragma unroll
        for (int p = 1; p < 32; p++) m = fmaxf(m, acc[p]);
        m = fmaxf(m + __ldg(b5 + oc), 0.0f);
        atomicMax(&g_pool[b * 1024 + oc], __float_as_int(m));
        __syncthreads();
    }
}

// ===========================================================================
// K4a: fc1 (1024 -> 512). One block per (output neuron, batch): 2048 blocks.
// 256 threads: one float4 of the weight row each; warp + smem reduce.
// ===========================================================================
__global__ __launch_bounds__(256) void k_fc1(const float* __restrict__ fw1,
                                             const float* __restrict__ fb1) {
    const int o = blockIdx.x, b = blockIdx.y, t = threadIdx.x;
    __shared__ float red[8];

    float4 w = __ldg((const float4*)(fw1 + (size_t)o * 1024) + t);
    float g0 = __int_as_float(g_pool[b * 1024 + 4 * t + 0]);
    float g1 = __int_as_float(g_pool[b * 1024 + 4 * t + 1]);
    float g2 = __int_as_float(g_pool[b * 1024 + 4 * t + 2]);
    float g3 = __int_as_float(g_pool[b * 1024 + 4 * t + 3]);
    float s = fmaf(w.x, g0, fmaf(w.y, g1, fmaf(w.z, g2, w.w * g3)));
#pragma unroll
    for (int off = 16; off > 0; off >>= 1)
        s += __shfl_down_sync(0xffffffffu, s, off);
    if ((t & 31) == 0) red[t >> 5] = s;
    __syncthreads();
    if (t == 0) {
        float acc = red[0];
#pragma unroll
        for (int j = 1; j < 8; j++) acc += red[j];
        g_a1[b * 512 + o] = fmaxf(acc + __ldg(fb1 + o), 0.0f);
    }
}

// ===========================================================================
// K4b: fc2 (512 -> 256). One block per (o, b): 1024 blocks, 128 threads.
// ===========================================================================
__global__ __launch_bounds__(128) void k_fc2(const float* __restrict__ fw2,
                                             const float* __restrict__ fb2) {
    const int o = blockIdx.x, b = blockIdx.y, t = threadIdx.x;
    __shared__ float red[4];

    float4 w = __ldg((const float4*)(fw2 + (size_t)o * 512) + t);
    const float* a1 = g_a1 + b * 512 + 4 * t;
    float s = fmaf(w.x, a1[0], fmaf(w.y, a1[1], fmaf(w.z, a1[2], w.w * a1[3])));
#pragma unroll
    for (int off = 16; off > 0; off >>= 1)
        s += __shfl_down_sync(0xffffffffu, s, off);
    if ((t & 31) == 0) red[t >> 5] = s;
    __syncthreads();
    if (t == 0) {
        float acc = ((red[0] + red[1]) + (red[2] + red[3]));
        g_a2[b * 256 + o] = fmaxf(acc + __ldg(fb2 + o), 0.0f);
    }
}

// ===========================================================================
// K4c: fc3 (256 -> 3). One block per batch; warp per output.
// ===========================================================================
__global__ __launch_bounds__(128) void k_fc3(const float* __restrict__ fw3,
                                             const float* __restrict__ fb3,
                                             float* __restrict__ out) {
    const int b = blockIdx.x, t = threadIdx.x;
    const int o = t >> 5, lane = t & 31;
    if (o >= 3) return;
    const float4* wr = (const float4*)(fw3 + (size_t)o * 256);
    const float* a2 = g_a2 + b * 256;
    float4 wA = __ldg(wr + lane);
    float4 wB = __ldg(wr + 32 + lane);
    float s = fmaf(wA.x, a2[4 * lane + 0], fmaf(wA.y, a2[4 * lane + 1],
              fmaf(wA.z, a2[4 * lane + 2], wA.w * a2[4 * lane + 3])));
    s = fmaf(wB.x, a2[128 + 4 * lane + 0], fmaf(wB.y, a2[128 + 4 * lane + 1],
        fmaf(wB.z, a2[128 + 4 * lane + 2], fmaf(wB.w, a2[128 + 4 * lane + 3], s))));
#pragma unroll
    for (int off = 16; off > 0; off >>= 1)
        s += __shfl_down_sync(0xffffffffu, s, off);
    if (lane == 0) out[b * 3 + o] = s + __ldg(fb3 + o);
}

// ===========================================================================
extern "C" void kernel_launch(void* const* d_in, const int* in_sizes, int n_in,
                              void* d_out, int out_size) {
    const float* x    = (const float*)d_in[0];
    const int*   far0 = (const int*)d_in[1];
    const float* w1 = (const float*)d_in[2];  const float* b1 = (const float*)d_in[3];
    const float* w2 = (const float*)d_in[4];  const float* b2 = (const float*)d_in[5];
    const float* w3 = (const float*)d_in[6];  const float* b3 = (const float*)d_in[7];
    const float* w4 = (const float*)d_in[8];  const float* b4 = (const float*)d_in[9];
    const float* w5 = (const float*)d_in[10]; const float* b5 = (const float*)d_in[11];
    const float* fw1 = (const float*)d_in[12]; const float* fb1 = (const float*)d_in[13];
    const float* fw2 = (const float*)d_in[14]; const float* fb2 = (const float*)d_in[15];
    const float* fw3 = (const float*)d_in[16]; const float* fb3 = (const float*)d_in[17];
    float* out = (float*)d_out;

    k_fps<<<NB + WARM_BLOCKS, 512>>>(x, far0, fw1, fw2, w5);
    k_fused<<<dim3(FUSED_GRID_X, NB), 512>>>(x, w1, b1, w2, b2, w3, b3, w4, b4);
    k_conv5<<<dim3(CONV5_GRID_X, NB), 128>>>(w5, b5);
    k_fc1<<<dim3(512, NB), 256>>>(fw1, fb1);
    k_fc2<<<dim3(256, NB), 128>>>(fw2, fb2);
    k_fc3<<<NB, 128>>>(fw3, fb3, out);
}